// round 4
// baseline (speedup 1.0000x reference)
#include <cuda_runtime.h>
#include <math.h>
#include <stdint.h>

#define N_NODES 50000
#define NE      800000
#define ETOT    850000
#define DIN     384
#define HID     256
#define HEADS   4
#define CDIM    64
#define EDIM    32
#define NLAYER  2
#define SLOPE   0.2f
#define TOT_H   (N_NODES*HID)

// ---------------- scratch ----------------------------------------------------
__device__ float    g_h   [(size_t)N_NODES*HID];
__device__ float    g_xlr [(size_t)N_NODES*512];
__device__ float    g_loopea[(size_t)N_NODES*EDIM];
__device__ float    g_deg [N_NODES];
__device__ float    g_logits[(size_t)ETOT*HEADS];
__device__ int      g_csr_ptr[N_NODES+1];
__device__ int      g_cursor [N_NODES];
__device__ int      g_csr_e [ETOT];
__device__ int      g_csr_s [ETOT];
__device__ float    g_wcat[(size_t)HID*512];
__device__ double   g_red[2];

// ---------------- helpers ----------------------------------------------------
__device__ __forceinline__ float lrelu(float x){ return x > 0.f ? x : SLOPE*x; }
__device__ __forceinline__ float sel4(float4 v, int h){
    return h==0 ? v.x : (h==1 ? v.y : (h==2 ? v.z : v.w));
}
__device__ __forceinline__ uint32_t f2tf(float f){
    uint32_t u; asm("cvt.rna.tf32.f32 %0, %1;" : "=r"(u) : "f"(f)); return u;
}
__device__ __forceinline__ void mma8(float* c, const uint4& a, uint32_t b0, uint32_t b1){
    asm volatile("mma.sync.aligned.m16n8k8.row.col.f32.tf32.tf32.f32 "
        "{%0,%1,%2,%3}, {%4,%5,%6,%7}, {%8,%9}, {%0,%1,%2,%3};"
        : "+f"(c[0]), "+f"(c[1]), "+f"(c[2]), "+f"(c[3])
        : "r"(a.x), "r"(a.y), "r"(a.z), "r"(a.w), "r"(b0), "r"(b1));
}

// ---------------- zero / setup ----------------------------------------------
__global__ void k_zero_f(float* p, size_t n){
    size_t i = (size_t)blockIdx.x*blockDim.x + threadIdx.x;
    if (i < n) p[i] = 0.f;
}
__global__ void k_zero_red(){ if (threadIdx.x < 2) g_red[threadIdx.x] = 0.0; }

__global__ void k_degree(const int* __restrict__ dst, const float* __restrict__ ea){
    int t = blockIdx.x*blockDim.x + threadIdx.x;
    if (t >= NE*8) return;
    int e = t >> 3, q = t & 7;
    int d = dst[e];
    float4 v = *(const float4*)(ea + (size_t)e*EDIM + q*4);
    float* base = g_loopea + (size_t)d*EDIM + q*4;
    atomicAdd(base+0, v.x); atomicAdd(base+1, v.y);
    atomicAdd(base+2, v.z); atomicAdd(base+3, v.w);
    if (q == 0) atomicAdd(&g_deg[d], 1.f);
}
__global__ void k_divloop(){
    int t = blockIdx.x*blockDim.x + threadIdx.x;
    if (t >= N_NODES*EDIM) return;
    float d = g_deg[t >> 5];
    g_loopea[t] = g_loopea[t] / fmaxf(d, 1.f);
}

__global__ void k_scan(){
    __shared__ int wsum[32];
    int tid = threadIdx.x, lane = tid & 31, w = tid >> 5;
    int carry = 0;
    if (tid == 0) g_csr_ptr[0] = 0;
    for (int base = 0; base < N_NODES; base += 1024) {
        int i = base + tid;
        int v = (i < N_NODES) ? ((int)g_deg[i] + 1) : 0;
        int x = v;
        #pragma unroll
        for (int off = 1; off < 32; off <<= 1) {
            int nb = __shfl_up_sync(0xffffffffu, x, off);
            if (lane >= off) x += nb;
        }
        if (lane == 31) wsum[w] = x;
        __syncthreads();
        if (w == 0) {
            int y = wsum[lane];
            #pragma unroll
            for (int off = 1; off < 32; off <<= 1) {
                int nb = __shfl_up_sync(0xffffffffu, y, off);
                if (lane >= off) y += nb;
            }
            wsum[lane] = y;
        }
        __syncthreads();
        int add  = (w > 0) ? wsum[w-1] : 0;
        int incl = carry + add + x;
        if (i < N_NODES) { g_csr_ptr[i+1] = incl; g_cursor[i] = incl - v; }
        carry += wsum[31];
        __syncthreads();
    }
}
__global__ void k_scatter(const int* __restrict__ src, const int* __restrict__ dst){
    int t = blockIdx.x*blockDim.x + threadIdx.x;
    if (t >= ETOT) return;
    int s, d;
    if (t < NE) { s = src[t]; d = dst[t]; } else { s = t - NE; d = s; }
    int pos = atomicAdd(&g_cursor[d], 1);
    g_csr_e[pos] = t;
    g_csr_s[pos] = s;
}

__global__ void k_catw(const float* __restrict__ wl, const float* __restrict__ wr){
    int t = blockIdx.x*blockDim.x + threadIdx.x;
    if (t >= HID*128) return;
    int k = t >> 7, q = t & 127;
    int c = q * 4;
    float4 v = (c < HID) ? *(const float4*)(wl + (size_t)k*HID + c)
                         : *(const float4*)(wr + (size_t)k*HID + (c - HID));
    *(float4*)(g_wcat + (size_t)k*512 + c) = v;
}

// ---------------- TF32 tensor-core GEMM: C = act(A@B + bias) -----------------
// 128x128 block tile, BK=16, 256 threads (8 warps, each 32x64).
// Smem holds A/B tiles pre-permuted into m16n8k8 fragment order.
__global__ __launch_bounds__(256) void tgemm(
    const float* __restrict__ A, const float* __restrict__ B,
    const float* __restrict__ bias, float* __restrict__ C,
    int M, int K, int Nn, int act)
{
    __shared__ uint4 Af[2][8][32];   // [kstep][mtile][thread]
    __shared__ uint4 Bf[2][8][32];   // [kstep][ntile-pair][thread]
    const int tid  = threadIdx.x;
    const int lane = tid & 31, wid = tid >> 5;
    const int wm = wid & 3, wn = wid >> 2;
    const int cRow = blockIdx.y * 128, cCol = blockIdx.x * 128;
    const int arow = tid >> 1, ah = tid & 1;
    const int brow = tid >> 4, bn0 = (tid & 15) * 8;
    const int q = lane & 3, g = lane >> 2;

    float acc[2][8][4];
    #pragma unroll
    for (int i = 0; i < 2; i++)
        #pragma unroll
        for (int j = 0; j < 8; j++)
            #pragma unroll
            for (int v = 0; v < 4; v++) acc[i][j][v] = 0.f;

    for (int kt = 0; kt < K; kt += 16) {
        float av[8], bv[8];
        {
            int gr = cRow + arow;
            if (gr < M) {
                const float* p = A + (size_t)gr*K + kt + ah*8;
                float4 x0 = *(const float4*)p, x1 = *(const float4*)(p+4);
                av[0]=x0.x; av[1]=x0.y; av[2]=x0.z; av[3]=x0.w;
                av[4]=x1.x; av[5]=x1.y; av[6]=x1.z; av[7]=x1.w;
            } else {
                #pragma unroll
                for (int c = 0; c < 8; c++) av[c] = 0.f;
            }
        }
        {
            const float* p = B + (size_t)(kt + brow)*Nn + cCol + bn0;
            float4 x0 = *(const float4*)p, x1 = *(const float4*)(p+4);
            bv[0]=x0.x; bv[1]=x0.y; bv[2]=x0.z; bv[3]=x0.w;
            bv[4]=x1.x; bv[5]=x1.y; bv[6]=x1.z; bv[7]=x1.w;
        }
        __syncthreads();
        {   // A scatter: all 8 values share ks = ah
            int mt = arow >> 4, rr = arow & 15;
            uint32_t* base = (uint32_t*)&Af[ah][mt][0];
            #pragma unroll
            for (int c = 0; c < 8; c++) {
                int slot = ((rr & 7) << 2) | (c & 3);
                int comp = (rr >> 3) | ((c >> 2) << 1);
                base[slot*4 + comp] = f2tf(av[c]);
            }
        }
        {   // B scatter: k = brow
            int ks = brow >> 3, kl = brow & 7;
            #pragma unroll
            for (int c = 0; c < 8; c++) {
                int n = bn0 + c;
                int nt = n >> 3;
                int slot = ((n & 7) << 2) | (kl & 3);
                int comp = (kl >> 2) | ((nt & 1) << 1);
                ((uint32_t*)&Bf[ks][nt >> 1][0])[slot*4 + comp] = f2tf(bv[c]);
            }
        }
        __syncthreads();
        #pragma unroll
        for (int ks = 0; ks < 2; ks++) {
            uint4 a0 = Af[ks][wm*2+0][lane];
            uint4 a1 = Af[ks][wm*2+1][lane];
            #pragma unroll
            for (int p = 0; p < 4; p++) {
                uint4 b = Bf[ks][wn*4+p][lane];
                mma8(acc[0][2*p+0], a0, b.x, b.y);
                mma8(acc[0][2*p+1], a0, b.z, b.w);
                mma8(acc[1][2*p+0], a1, b.x, b.y);
                mma8(acc[1][2*p+1], a1, b.z, b.w);
            }
        }
    }
    #pragma unroll
    for (int i = 0; i < 2; i++) {
        int r0 = cRow + wm*32 + i*16 + g;
        #pragma unroll
        for (int j = 0; j < 8; j++) {
            int col = cCol + wn*64 + j*8 + 2*q;
            float bx = 0.f, by = 0.f;
            if (bias) { float2 bb = *(const float2*)(bias + col); bx = bb.x; by = bb.y; }
            float v0 = acc[i][j][0] + bx, v1 = acc[i][j][1] + by;
            float v2 = acc[i][j][2] + bx, v3 = acc[i][j][3] + by;
            if (act == 1) {
                v0 = fmaxf(v0,0.f); v1 = fmaxf(v1,0.f);
                v2 = fmaxf(v2,0.f); v3 = fmaxf(v3,0.f);
            }
            if (r0 < M)     *(float2*)(C + (size_t)r0*Nn + col)     = make_float2(v0,v1);
            if (r0+8 < M)   *(float2*)(C + (size_t)(r0+8)*Nn + col) = make_float2(v2,v3);
        }
    }
}

// ---------------- fused ep-GEMM (tf32 mma) + logits --------------------------
// 128 edges/block; ep = ea2@we on tensor cores; epilogue gathers xl/xr per
// fragment, computes logits with quad-shfl reduce.
__global__ __launch_bounds__(256) void k_eplogits(
    const int* __restrict__ src, const int* __restrict__ dst,
    const float* __restrict__ ea, const float* __restrict__ we,
    const float* __restrict__ attL)
{
    __shared__ uint4 Af[4][8][32];        // 16 KB  [ks][mtile][thread]
    __shared__ uint4 Bf[4][2][8][32];     // 32 KB  [ks][half][ntp][thread]
    __shared__ int s_src[128], s_dst[128];
    const int tid = threadIdx.x;
    const int lane = tid & 31, wid = tid >> 5;
    const int q = lane & 3, g = lane >> 2;
    const int e0 = blockIdx.x * 128;

    for (int i = tid; i < 128; i += 256) {
        int ge = e0 + i, s = 0, d = 0;
        if (ge < ETOT) {
            if (ge < NE) { s = src[ge]; d = dst[ge]; } else { s = ge - NE; d = s; }
        }
        s_src[i] = s; s_dst[i] = d;
    }
    {   // stage ea tile: row = tid/2, k half = tid&1 (16 k each)
        int row = tid >> 1, kh = tid & 1;
        int ge = e0 + row;
        float av[16];
        if (ge < ETOT) {
            const float* p = ((ge < NE) ? (ea + (size_t)ge*EDIM)
                                        : (g_loopea + (size_t)(ge - NE)*EDIM)) + kh*16;
            #pragma unroll
            for (int c4 = 0; c4 < 4; c4++) {
                float4 v = *(const float4*)(p + c4*4);
                av[c4*4+0]=v.x; av[c4*4+1]=v.y; av[c4*4+2]=v.z; av[c4*4+3]=v.w;
            }
        } else {
            #pragma unroll
            for (int c = 0; c < 16; c++) av[c] = 0.f;
        }
        int mt = row >> 4, rr = row & 15;
        #pragma unroll
        for (int c = 0; c < 16; c++) {
            int k  = kh*16 + c;
            int ks = k >> 3, kl = k & 7;
            int slot = ((rr & 7) << 2) | (kl & 3);
            int comp = (rr >> 3) | ((kl >> 2) << 1);
            ((uint32_t*)&Af[ks][mt][0])[slot*4 + comp] = f2tf(av[c]);
        }
    }
    {   // stage we: k = tid/8 (0..31), n0 = (tid&7)*32
        int k = tid >> 3, n0 = (tid & 7) * 32;
        int ks = k >> 3, kl = k & 7;
        #pragma unroll
        for (int c4 = 0; c4 < 8; c4++) {
            float4 v = *(const float4*)(we + (size_t)k*HID + n0 + c4*4);
            float vv[4] = {v.x, v.y, v.z, v.w};
            #pragma unroll
            for (int c = 0; c < 4; c++) {
                int n = n0 + c4*4 + c;
                int half = n >> 7, ntl = (n & 127) >> 3;
                int slot = ((n & 7) << 2) | (kl & 3);
                int comp = (kl >> 2) | ((ntl & 1) << 1);
                ((uint32_t*)&Bf[ks][half][ntl >> 1][0])[slot*4 + comp] = f2tf(vv[c]);
            }
        }
    }
    __syncthreads();

    const int r0l = wid*16 + g, r1l = r0l + 8;
    const int s0 = s_src[r0l], d0 = s_dst[r0l];
    const int s1 = s_src[r1l], d1 = s_dst[r1l];

    for (int half = 0; half < 2; half++) {
        float acc[16][4];
        #pragma unroll
        for (int j = 0; j < 16; j++)
            #pragma unroll
            for (int v = 0; v < 4; v++) acc[j][v] = 0.f;
        #pragma unroll
        for (int ks = 0; ks < 4; ks++) {
            uint4 a = Af[ks][wid][lane];
            #pragma unroll
            for (int p = 0; p < 8; p++) {
                uint4 b = Bf[ks][half][p][lane];
                mma8(acc[2*p+0], a, b.x, b.y);
                mma8(acc[2*p+1], a, b.z, b.w);
            }
        }
        float p00 = 0.f, p01 = 0.f, p10 = 0.f, p11 = 0.f;
        #pragma unroll
        for (int j = 0; j < 16; j++) {
            int cb = half*128 + j*8 + 2*q;
            float2 at  = *(const float2*)(attL + cb);
            float2 xl0 = *(const float2*)(g_xlr + (size_t)s0*512 + cb);
            float2 xr0 = *(const float2*)(g_xlr + (size_t)d0*512 + 256 + cb);
            float c0 = lrelu(acc[j][0] + xl0.x + xr0.x)*at.x
                     + lrelu(acc[j][1] + xl0.y + xr0.y)*at.y;
            float2 xl1 = *(const float2*)(g_xlr + (size_t)s1*512 + cb);
            float2 xr1 = *(const float2*)(g_xlr + (size_t)d1*512 + 256 + cb);
            float c1 = lrelu(acc[j][2] + xl1.x + xr1.x)*at.x
                     + lrelu(acc[j][3] + xl1.y + xr1.y)*at.y;
            if (j < 8) { p00 += c0; p10 += c1; } else { p01 += c0; p11 += c1; }
        }
        #pragma unroll
        for (int off = 1; off <= 2; off <<= 1) {
            p00 += __shfl_xor_sync(0xffffffffu, p00, off);
            p01 += __shfl_xor_sync(0xffffffffu, p01, off);
            p10 += __shfl_xor_sync(0xffffffffu, p10, off);
            p11 += __shfl_xor_sync(0xffffffffu, p11, off);
        }
        if (q == 0) {
            if (e0 + r0l < ETOT) {
                g_logits[(size_t)(e0 + r0l)*HEADS + half*2 + 0] = p00;
                g_logits[(size_t)(e0 + r0l)*HEADS + half*2 + 1] = p01;
            }
            if (e0 + r1l < ETOT) {
                g_logits[(size_t)(e0 + r1l)*HEADS + half*2 + 0] = p10;
                g_logits[(size_t)(e0 + r1l)*HEADS + half*2 + 1] = p11;
            }
        }
    }
}

// ---------------- node aggregation (unchanged) -------------------------------
__global__ __launch_bounds__(256) void k_nodeagg(const float* __restrict__ bconv){
    const int n    = (blockIdx.x*256 + threadIdx.x) >> 5;
    const int lane = threadIdx.x & 31;
    const int p0 = g_csr_ptr[n], p1 = g_csr_ptr[n+1];
    float4 mx = make_float4(-1e30f,-1e30f,-1e30f,-1e30f);
    for (int idx = p0 + lane; idx < p1; idx += 32) {
        int e = g_csr_e[idx];
        float4 lg = *(const float4*)(g_logits + (size_t)e*HEADS);
        mx.x = fmaxf(mx.x, lg.x); mx.y = fmaxf(mx.y, lg.y);
        mx.z = fmaxf(mx.z, lg.z); mx.w = fmaxf(mx.w, lg.w);
    }
    #pragma unroll
    for (int off = 16; off; off >>= 1) {
        mx.x = fmaxf(mx.x, __shfl_xor_sync(0xffffffffu, mx.x, off));
        mx.y = fmaxf(mx.y, __shfl_xor_sync(0xffffffffu, mx.y, off));
        mx.z = fmaxf(mx.z, __shfl_xor_sync(0xffffffffu, mx.z, off));
        mx.w = fmaxf(mx.w, __shfl_xor_sync(0xffffffffu, mx.w, off));
    }
    float4 sm = make_float4(0,0,0,0);
    for (int idx = p0 + lane; idx < p1; idx += 32) {
        int e = g_csr_e[idx];
        float4 lg = *(const float4*)(g_logits + (size_t)e*HEADS);
        sm.x += expf(lg.x - mx.x); sm.y += expf(lg.y - mx.y);
        sm.z += expf(lg.z - mx.z); sm.w += expf(lg.w - mx.w);
    }
    #pragma unroll
    for (int off = 16; off; off >>= 1) {
        sm.x += __shfl_xor_sync(0xffffffffu, sm.x, off);
        sm.y += __shfl_xor_sync(0xffffffffu, sm.y, off);
        sm.z += __shfl_xor_sync(0xffffffffu, sm.z, off);
        sm.w += __shfl_xor_sync(0xffffffffu, sm.w, off);
    }
    const int head = lane >> 3;
    const float mh = sel4(mx, head);
    const float ih = 1.f / (sel4(sm, head) + 1e-16f);
    float acc[8];
    #pragma unroll
    for (int j = 0; j < 8; j++) acc[j] = 0.f;
    for (int idx = p0; idx < p1; idx++) {
        int e = g_csr_e[idx];
        int s = g_csr_s[idx];
        float4 lg = *(const float4*)(g_logits + (size_t)e*HEADS);
        float w = expf(sel4(lg, head) - mh) * ih;
        const float* px = g_xlr + (size_t)s*512 + lane*8;
        float4 x0 = *(const float4*)(px);
        float4 x1 = *(const float4*)(px+4);
        acc[0] += w*x0.x; acc[1] += w*x0.y; acc[2] += w*x0.z; acc[3] += w*x0.w;
        acc[4] += w*x1.x; acc[5] += w*x1.y; acc[6] += w*x1.z; acc[7] += w*x1.w;
    }
    float* ph = g_h + (size_t)n*HID + lane*8;
    float4 h0 = *(const float4*)(ph);
    float4 h1 = *(const float4*)(ph+4);
    float4 b0 = *(const float4*)(bconv + lane*8);
    float4 b1 = *(const float4*)(bconv + lane*8 + 4);
    float hv[8] = {h0.x,h0.y,h0.z,h0.w,h1.x,h1.y,h1.z,h1.w};
    float bv[8] = {b0.x,b0.y,b0.z,b0.w,b1.x,b1.y,b1.z,b1.w};
    float s_ = 0.f, q_ = 0.f;
    float out8[8];
    #pragma unroll
    for (int j = 0; j < 8; j++) {
        float v  = acc[j] + bv[j];
        float el = v > 0.f ? v : (expf(v) - 1.f);
        float t  = hv[j] + el;
        out8[j] = t; s_ += t; q_ += t*t;
    }
    *(float4*)(ph)   = make_float4(out8[0],out8[1],out8[2],out8[3]);
    *(float4*)(ph+4) = make_float4(out8[4],out8[5],out8[6],out8[7]);
    #pragma unroll
    for (int off = 16; off; off >>= 1) {
        s_ += __shfl_down_sync(0xffffffffu, s_, off);
        q_ += __shfl_down_sync(0xffffffffu, q_, off);
    }
    __shared__ float ss[8], sq[8];
    int w = threadIdx.x >> 5;
    if (lane == 0) { ss[w] = s_; sq[w] = q_; }
    __syncthreads();
    if (threadIdx.x == 0) {
        float S = 0.f, Q = 0.f;
        #pragma unroll
        for (int i = 0; i < 8; i++) { S += ss[i]; Q += sq[i]; }
        atomicAdd(&g_red[0], (double)S);
        atomicAdd(&g_red[1], (double)Q);
    }
}

__global__ void k_norm(const float* __restrict__ lnw, const float* __restrict__ lnb){
    int idx = blockIdx.x*blockDim.x + threadIdx.x;
    if (idx >= TOT_H) return;
    int c = idx & (HID-1);
    double M  = (double)TOT_H;
    double mu = g_red[0] / M;
    double var = g_red[1] / M - mu*mu;
    if (var < 0.0) var = 0.0;
    float rs = (float)(1.0 / (sqrt(var) + 1e-5));
    g_h[idx] = (g_h[idx] - (float)mu) * rs * lnw[c] + lnb[c];
}

// ---------------- launcher ---------------------------------------------------
extern "C" void kernel_launch(void* const* d_in, const int* in_sizes, int n_in,
                              void* d_out, int out_size)
{
    const float* x     = (const float*)d_in[0];
    const int*   ei    = (const int*)  d_in[1];
    const float* ea    = (const float*)d_in[2];
    const float* w_in  = (const float*)d_in[3];
    const float* b_in  = (const float*)d_in[4];
    const float* wl    = (const float*)d_in[5];
    const float* wr    = (const float*)d_in[6];
    const float* we    = (const float*)d_in[7];
    const float* att   = (const float*)d_in[8];
    const float* bconv = (const float*)d_in[9];
    const float* lnw   = (const float*)d_in[10];
    const float* lnb   = (const float*)d_in[11];
    const float* wout  = (const float*)d_in[12];
    const float* bout  = (const float*)d_in[13];
    float* out = (float*)d_out;
    const int* srcA = ei;
    const int* dstA = ei + NE;

    float *p_h, *p_xlr, *p_loop, *p_deg, *p_wcat;
    cudaGetSymbolAddress((void**)&p_h,    g_h);
    cudaGetSymbolAddress((void**)&p_xlr,  g_xlr);
    cudaGetSymbolAddress((void**)&p_loop, g_loopea);
    cudaGetSymbolAddress((void**)&p_deg,  g_deg);
    cudaGetSymbolAddress((void**)&p_wcat, g_wcat);

    k_zero_f<<<(unsigned)(((size_t)N_NODES*EDIM + 511)/512), 512>>>(p_loop, (size_t)N_NODES*EDIM);
    k_zero_f<<<(N_NODES + 511)/512, 512>>>(p_deg, (size_t)N_NODES);
    k_degree<<<(NE*8 + 255)/256, 256>>>(dstA, ea);
    k_divloop<<<(N_NODES*EDIM + 255)/256, 256>>>();
    k_scan<<<1, 1024>>>();
    k_scatter<<<(ETOT + 255)/256, 256>>>(srcA, dstA);

    dim3 gIn (HID/128, (N_NODES + 127)/128);
    dim3 gXlr(512/128, (N_NODES + 127)/128);
    tgemm<<<gIn, 256>>>(x, w_in, b_in, p_h, N_NODES, DIN, HID, 1);

    for (int l = 0; l < NLAYER; l++) {
        k_catw<<<(HID*128 + 255)/256, 256>>>(wl + (size_t)l*HID*HID,
                                             wr + (size_t)l*HID*HID);
        tgemm<<<gXlr, 256>>>(p_h, p_wcat, nullptr, p_xlr, N_NODES, HID, 512, 0);
        k_eplogits<<<(ETOT + 127)/128, 256>>>(srcA, dstA, ea,
                                              we + (size_t)l*EDIM*HID,
                                              att + (size_t)l*HEADS*CDIM);
        k_zero_red<<<1, 32>>>();
        k_nodeagg<<<N_NODES/8, 256>>>(bconv + (size_t)l*HID);
        k_norm<<<TOT_H/256, 256>>>(lnw + (size_t)l*HID, lnb + (size_t)l*HID);
    }
    tgemm<<<gIn, 256>>>(p_h, wout, bout, out, N_NODES, HID, HID, 0);
}

// round 5
// speedup vs baseline: 1.7946x; 1.7946x over previous
#include <cuda_runtime.h>
#include <math.h>
#include <stdint.h>

#define N_NODES 50000
#define NE      800000
#define ETOT    850000
#define DIN     384
#define HID     256
#define HEADS   4
#define CDIM    64
#define EDIM    32
#define NLAYER  2
#define SLOPE   0.2f
#define TOT_H   (N_NODES*HID)

// ---------------- scratch ----------------------------------------------------
__device__ float    g_h   [(size_t)N_NODES*HID];
__device__ float    g_xlr [(size_t)N_NODES*512];
__device__ float    g_loopea[(size_t)N_NODES*EDIM];
__device__ float    g_deg [N_NODES];
__device__ float    g_logits[(size_t)ETOT*HEADS];
__device__ int      g_csr_ptr[N_NODES+1];
__device__ int      g_cursor [N_NODES];
__device__ int      g_csr_e [ETOT];
__device__ int      g_csr_s [ETOT];
__device__ float    g_winT [(size_t)HID*DIN];    // [256][384] tf32
__device__ float    g_wcatT[(size_t)512*HID];    // [512][256] tf32 (wl^T | wr^T)
__device__ float    g_weT  [(size_t)HID*EDIM];   // [256][32]  tf32
__device__ float    g_woutT[(size_t)HID*HID];    // [256][256] tf32
__device__ double   g_red[2];

// ---------------- helpers ----------------------------------------------------
__device__ __forceinline__ float lrelu(float x){ return x > 0.f ? x : SLOPE*x; }
__device__ __forceinline__ float sel4(float4 v, int h){
    return h==0 ? v.x : (h==1 ? v.y : (h==2 ? v.z : v.w));
}
__device__ __forceinline__ uint32_t f2tf(float f){
    uint32_t u; asm("cvt.rna.tf32.f32 %0, %1;" : "=r"(u) : "f"(f)); return u;
}
__device__ __forceinline__ float tfF(float f){ return __uint_as_float(f2tf(f)); }
__device__ __forceinline__ uint32_t sptr(const void* p){
    return (uint32_t)__cvta_generic_to_shared(p);
}
__device__ __forceinline__ void mma8(float* c, const uint4& a, uint32_t b0, uint32_t b1){
    asm volatile("mma.sync.aligned.m16n8k8.row.col.f32.tf32.tf32.f32 "
        "{%0,%1,%2,%3}, {%4,%5,%6,%7}, {%8,%9}, {%0,%1,%2,%3};"
        : "+f"(c[0]), "+f"(c[1]), "+f"(c[2]), "+f"(c[3])
        : "r"(a.x), "r"(a.y), "r"(a.z), "r"(a.w), "r"(b0), "r"(b1));
}
#define LDSM4(d, addr) \
    asm volatile("ldmatrix.sync.aligned.m8n8.x4.shared.b16 {%0,%1,%2,%3}, [%4];" \
        : "=r"((d).x), "=r"((d).y), "=r"((d).z), "=r"((d).w) : "r"(addr))

// ---------------- zero / setup ----------------------------------------------
__global__ void k_zero_f(float* p, size_t n){
    size_t i = (size_t)blockIdx.x*blockDim.x + threadIdx.x;
    if (i < n) p[i] = 0.f;
}
__global__ void k_zero_red(){ if (threadIdx.x < 2) g_red[threadIdx.x] = 0.0; }

__global__ void k_degree(const int* __restrict__ dst, const float* __restrict__ ea){
    int t = blockIdx.x*blockDim.x + threadIdx.x;
    if (t >= NE*8) return;
    int e = t >> 3, q = t & 7;
    int d = dst[e];
    float4 v = *(const float4*)(ea + (size_t)e*EDIM + q*4);
    float* base = g_loopea + (size_t)d*EDIM + q*4;
    atomicAdd(base+0, v.x); atomicAdd(base+1, v.y);
    atomicAdd(base+2, v.z); atomicAdd(base+3, v.w);
    if (q == 0) atomicAdd(&g_deg[d], 1.f);
}
__global__ void k_divloop(){
    int t = blockIdx.x*blockDim.x + threadIdx.x;
    if (t >= N_NODES*EDIM) return;
    float d = g_deg[t >> 5];
    g_loopea[t] = g_loopea[t] / fmaxf(d, 1.f);
}

__global__ void k_scan(){
    __shared__ int wsum[32];
    int tid = threadIdx.x, lane = tid & 31, w = tid >> 5;
    int carry = 0;
    if (tid == 0) g_csr_ptr[0] = 0;
    for (int base = 0; base < N_NODES; base += 1024) {
        int i = base + tid;
        int v = (i < N_NODES) ? ((int)g_deg[i] + 1) : 0;
        int x = v;
        #pragma unroll
        for (int off = 1; off < 32; off <<= 1) {
            int nb = __shfl_up_sync(0xffffffffu, x, off);
            if (lane >= off) x += nb;
        }
        if (lane == 31) wsum[w] = x;
        __syncthreads();
        if (w == 0) {
            int y = wsum[lane];
            #pragma unroll
            for (int off = 1; off < 32; off <<= 1) {
                int nb = __shfl_up_sync(0xffffffffu, y, off);
                if (lane >= off) y += nb;
            }
            wsum[lane] = y;
        }
        __syncthreads();
        int add  = (w > 0) ? wsum[w-1] : 0;
        int incl = carry + add + x;
        if (i < N_NODES) { g_csr_ptr[i+1] = incl; g_cursor[i] = incl - v; }
        carry += wsum[31];
        __syncthreads();
    }
}
__global__ void k_scatter(const int* __restrict__ src, const int* __restrict__ dst){
    int t = blockIdx.x*blockDim.x + threadIdx.x;
    if (t >= ETOT) return;
    int s, d;
    if (t < NE) { s = src[t]; d = dst[t]; } else { s = t - NE; d = s; }
    int pos = atomicAdd(&g_cursor[d], 1);
    g_csr_e[pos] = t;
    g_csr_s[pos] = s;
}

// ---------------- weight prep: transpose + tf32 round ------------------------
// in [K][N] -> out [N][K]; K,N multiples of 32. 256 threads.
__global__ void k_transpose(const float* __restrict__ in, float* __restrict__ out,
                            int K, int N){
    __shared__ float t[32][33];
    int kb = blockIdx.y*32, nb = blockIdx.x*32;
    int tx = threadIdx.x & 31, ty = threadIdx.x >> 5;
    #pragma unroll
    for (int i = ty; i < 32; i += 8)
        t[i][tx] = in[(size_t)(kb+i)*N + nb + tx];
    __syncthreads();
    #pragma unroll
    for (int i = ty; i < 32; i += 8)
        out[(size_t)(nb+i)*K + kb + tx] = tfF(t[tx][i]);
}
// weT [256][32] from we [32][256] (tiny)
__global__ void k_weT(const float* __restrict__ we){
    int t = blockIdx.x*blockDim.x + threadIdx.x;   // 8192
    if (t >= HID*EDIM) return;
    int n = t >> 5, k = t & 31;
    g_weT[t] = tfF(we[(size_t)k*HID + n]);
}

// ---------------- TF32 LDSM GEMM: C = act(A @ Bt^T + bias) -------------------
// A [M][K] row-major f32; Bt [N][K] row-major, pre-rounded tf32.
// 128x128 tile, BK=16, 256 thr (8 warps = 2M x 4N of 64x32).
#define APAD 20
__global__ __launch_bounds__(256) void tgemm(
    const float* __restrict__ A, const float* __restrict__ Bt,
    const float* __restrict__ bias, float* __restrict__ C,
    int M, int K, int Nn, int act)
{
    __shared__ float As[2][128*APAD];
    __shared__ float Bs[2][128*APAD];
    const int tid = threadIdx.x, lane = tid & 31, wid = tid >> 5;
    const int wm = (wid & 1)*64, wn = (wid >> 1)*32;
    const int cRow = blockIdx.y*128, cCol = blockIdx.x*128;
    const int r0 = tid >> 2, q0 = tid & 3;

    const int aoff = ((wm + (lane & 15))*APAD + ((lane >> 4) << 2))*4;
    const int boff = ((wn + (lane & 15))*APAD + ((lane >> 4) << 2))*4;

    float acc[4][4][4];
    #pragma unroll
    for (int i = 0; i < 4; i++)
        #pragma unroll
        for (int j = 0; j < 4; j++)
            #pragma unroll
            for (int v = 0; v < 4; v++) acc[i][j][v] = 0.f;

    float4 aR0, aR1, bR0, bR1;
#define LDG_TILE(kt) { \
    int gr0 = cRow + r0, gr1 = gr0 + 64; \
    aR0 = (gr0 < M) ? *(const float4*)(A + (size_t)gr0*K + (kt) + q0*4) : make_float4(0,0,0,0); \
    aR1 = (gr1 < M) ? *(const float4*)(A + (size_t)gr1*K + (kt) + q0*4) : make_float4(0,0,0,0); \
    bR0 = *(const float4*)(Bt + (size_t)(cCol + r0)*K + (kt) + q0*4); \
    bR1 = *(const float4*)(Bt + (size_t)(cCol + r0 + 64)*K + (kt) + q0*4); }
#define STS_TILE(b) { \
    float* pa = &As[b][r0*APAD + q0*4]; \
    *(float4*)pa = make_float4(tfF(aR0.x), tfF(aR0.y), tfF(aR0.z), tfF(aR0.w)); \
    *(float4*)(pa + 64*APAD) = make_float4(tfF(aR1.x), tfF(aR1.y), tfF(aR1.z), tfF(aR1.w)); \
    float* pb = &Bs[b][r0*APAD + q0*4]; \
    *(float4*)pb = bR0; \
    *(float4*)(pb + 64*APAD) = bR1; }
#define COMPUTE(b) { \
    uint32_t ab = sptr(&As[b][0]) + aoff; \
    uint32_t bb = sptr(&Bs[b][0]) + boff; \
    _Pragma("unroll") \
    for (int ks = 0; ks < 2; ks++) { \
        uint4 af0, af1, af2, af3, bf0, bf1; \
        LDSM4(af0, ab + (ks*8)*4); \
        LDSM4(af1, ab + (16*APAD + ks*8)*4); \
        LDSM4(af2, ab + (32*APAD + ks*8)*4); \
        LDSM4(af3, ab + (48*APAD + ks*8)*4); \
        LDSM4(bf0, bb + (ks*8)*4); \
        LDSM4(bf1, bb + (16*APAD + ks*8)*4); \
        mma8(acc[0][0], af0, bf0.x, bf0.z); mma8(acc[0][1], af0, bf0.y, bf0.w); \
        mma8(acc[0][2], af0, bf1.x, bf1.z); mma8(acc[0][3], af0, bf1.y, bf1.w); \
        mma8(acc[1][0], af1, bf0.x, bf0.z); mma8(acc[1][1], af1, bf0.y, bf0.w); \
        mma8(acc[1][2], af1, bf1.x, bf1.z); mma8(acc[1][3], af1, bf1.y, bf1.w); \
        mma8(acc[2][0], af2, bf0.x, bf0.z); mma8(acc[2][1], af2, bf0.y, bf0.w); \
        mma8(acc[2][2], af2, bf1.x, bf1.z); mma8(acc[2][3], af2, bf1.y, bf1.w); \
        mma8(acc[3][0], af3, bf0.x, bf0.z); mma8(acc[3][1], af3, bf0.y, bf0.w); \
        mma8(acc[3][2], af3, bf1.x, bf1.z); mma8(acc[3][3], af3, bf1.y, bf1.w); \
    } }

    LDG_TILE(0);
    STS_TILE(0);
    __syncthreads();
    int buf = 0;
    for (int kt = 16; kt < K; kt += 16) {
        LDG_TILE(kt);
        COMPUTE(buf);
        STS_TILE(buf ^ 1);
        __syncthreads();
        buf ^= 1;
    }
    COMPUTE(buf);

    const int g = lane >> 2, q = lane & 3;
    #pragma unroll
    for (int mf = 0; mf < 4; mf++) {
        int rA = cRow + wm + mf*16 + g;
        #pragma unroll
        for (int nf = 0; nf < 4; nf++) {
            int col = cCol + wn + nf*8 + 2*q;
            float bx = 0.f, by = 0.f;
            if (bias) { float2 bb = *(const float2*)(bias + col); bx = bb.x; by = bb.y; }
            float v0 = acc[mf][nf][0] + bx, v1 = acc[mf][nf][1] + by;
            float v2 = acc[mf][nf][2] + bx, v3 = acc[mf][nf][3] + by;
            if (act == 1) {
                v0 = fmaxf(v0,0.f); v1 = fmaxf(v1,0.f);
                v2 = fmaxf(v2,0.f); v3 = fmaxf(v3,0.f);
            }
            if (rA < M)     *(float2*)(C + (size_t)rA*Nn + col)     = make_float2(v0,v1);
            if (rA+8 < M)   *(float2*)(C + (size_t)(rA+8)*Nn + col) = make_float2(v2,v3);
        }
    }
#undef LDG_TILE
#undef STS_TILE
#undef COMPUTE
}

// ---------------- fused ep-GEMM (LDSM tf32) + logits -------------------------
#define EPAD 36
__global__ __launch_bounds__(256) void k_eplogits(
    const int* __restrict__ src, const int* __restrict__ dst,
    const float* __restrict__ ea, const float* __restrict__ attL)
{
    __shared__ float As[128*EPAD];    // 18 KB ea tile (tf32)
    __shared__ float Bs[128*EPAD];    // 18 KB weT half
    __shared__ int s_src[128], s_dst[128];
    const int tid = threadIdx.x, lane = tid & 31, wid = tid >> 5;
    const int q = lane & 3, g = lane >> 2;
    const int e0 = blockIdx.x * 128;

    for (int i = tid; i < 128; i += 256) {
        int ge = e0 + i, s = 0, d = 0;
        if (ge < ETOT) {
            if (ge < NE) { s = src[ge]; d = dst[ge]; } else { s = ge - NE; d = s; }
        }
        s_src[i] = s; s_dst[i] = d;
    }
    // stage ea (tf32): 1024 float4s, 4 per thread
    #pragma unroll
    for (int i = 0; i < 4; i++) {
        int f = tid + i*256;
        int row = f >> 3, q8 = f & 7;
        int ge = e0 + row;
        float4 v = make_float4(0,0,0,0);
        if (ge < ETOT) {
            const float* p = (ge < NE) ? (ea + (size_t)ge*EDIM)
                                       : (g_loopea + (size_t)(ge - NE)*EDIM);
            v = *(const float4*)(p + q8*4);
        }
        *(float4*)(&As[row*EPAD + q8*4]) =
            make_float4(tfF(v.x), tfF(v.y), tfF(v.z), tfF(v.w));
    }
    __syncthreads();

    const int aoff = ((wid*16 + (lane & 15))*EPAD + ((lane >> 4) << 2))*4;
    const int boff = (((lane & 15))*EPAD + ((lane >> 4) << 2))*4;
    const int r0l = wid*16 + g, r1l = r0l + 8;
    const int s0 = s_src[r0l], d0 = s_dst[r0l];
    const int s1 = s_src[r1l], d1 = s_dst[r1l];

    for (int half = 0; half < 2; half++) {
        if (half) __syncthreads();
        // stage weT half: rows n = half*128 + 0..127, 32 k each (pre-tf32)
        #pragma unroll
        for (int i = 0; i < 4; i++) {
            int f = tid + i*256;
            int row = f >> 3, q8 = f & 7;
            *(float4*)(&Bs[row*EPAD + q8*4]) =
                *(const float4*)(g_weT + (size_t)(half*128 + row)*EDIM + q8*4);
        }
        __syncthreads();

        float acc[16][4];
        #pragma unroll
        for (int j = 0; j < 16; j++)
            #pragma unroll
            for (int v = 0; v < 4; v++) acc[j][v] = 0.f;
        uint32_t ab = sptr(&As[0]) + aoff;
        uint32_t bb = sptr(&Bs[0]) + boff;
        #pragma unroll
        for (int ks = 0; ks < 4; ks++) {
            uint4 a;
            LDSM4(a, ab + (ks*8)*4);
            #pragma unroll
            for (int nt = 0; nt < 8; nt++) {
                uint4 b;
                LDSM4(b, bb + (nt*16*EPAD + ks*8)*4);
                mma8(acc[nt*2+0], a, b.x, b.z);
                mma8(acc[nt*2+1], a, b.y, b.w);
            }
        }
        // epilogue
        float p00 = 0.f, p01 = 0.f, p10 = 0.f, p11 = 0.f;
        #pragma unroll
        for (int j = 0; j < 16; j++) {
            int cb = half*128 + j*8 + 2*q;
            float2 at  = *(const float2*)(attL + cb);
            float2 xl0 = *(const float2*)(g_xlr + (size_t)s0*512 + cb);
            float2 xr0 = *(const float2*)(g_xlr + (size_t)d0*512 + 256 + cb);
            float c0 = lrelu(acc[j][0] + xl0.x + xr0.x)*at.x
                     + lrelu(acc[j][1] + xl0.y + xr0.y)*at.y;
            float2 xl1 = *(const float2*)(g_xlr + (size_t)s1*512 + cb);
            float2 xr1 = *(const float2*)(g_xlr + (size_t)d1*512 + 256 + cb);
            float c1 = lrelu(acc[j][2] + xl1.x + xr1.x)*at.x
                     + lrelu(acc[j][3] + xl1.y + xr1.y)*at.y;
            if (j < 8) { p00 += c0; p10 += c1; } else { p01 += c0; p11 += c1; }
        }
        #pragma unroll
        for (int off = 1; off <= 2; off <<= 1) {
            p00 += __shfl_xor_sync(0xffffffffu, p00, off);
            p01 += __shfl_xor_sync(0xffffffffu, p01, off);
            p10 += __shfl_xor_sync(0xffffffffu, p10, off);
            p11 += __shfl_xor_sync(0xffffffffu, p11, off);
        }
        if (q == 0) {
            if (e0 + r0l < ETOT) {
                g_logits[(size_t)(e0 + r0l)*HEADS + half*2 + 0] = p00;
                g_logits[(size_t)(e0 + r0l)*HEADS + half*2 + 1] = p01;
            }
            if (e0 + r1l < ETOT) {
                g_logits[(size_t)(e0 + r1l)*HEADS + half*2 + 0] = p10;
                g_logits[(size_t)(e0 + r1l)*HEADS + half*2 + 1] = p11;
            }
        }
    }
}

// ---------------- node aggregation -------------------------------------------
__global__ __launch_bounds__(256) void k_nodeagg(const float* __restrict__ bconv){
    const int n    = (blockIdx.x*256 + threadIdx.x) >> 5;
    const int lane = threadIdx.x & 31;
    const int p0 = g_csr_ptr[n], p1 = g_csr_ptr[n+1];
    float4 mx = make_float4(-1e30f,-1e30f,-1e30f,-1e30f);
    for (int idx = p0 + lane; idx < p1; idx += 32) {
        int e = g_csr_e[idx];
        float4 lg = *(const float4*)(g_logits + (size_t)e*HEADS);
        mx.x = fmaxf(mx.x, lg.x); mx.y = fmaxf(mx.y, lg.y);
        mx.z = fmaxf(mx.z, lg.z); mx.w = fmaxf(mx.w, lg.w);
    }
    #pragma unroll
    for (int off = 16; off; off >>= 1) {
        mx.x = fmaxf(mx.x, __shfl_xor_sync(0xffffffffu, mx.x, off));
        mx.y = fmaxf(mx.y, __shfl_xor_sync(0xffffffffu, mx.y, off));
        mx.z = fmaxf(mx.z, __shfl_xor_sync(0xffffffffu, mx.z, off));
        mx.w = fmaxf(mx.w, __shfl_xor_sync(0xffffffffu, mx.w, off));
    }
    float4 sm = make_float4(0,0,0,0);
    for (int idx = p0 + lane; idx < p1; idx += 32) {
        int e = g_csr_e[idx];
        float4 lg = *(const float4*)(g_logits + (size_t)e*HEADS);
        sm.x += expf(lg.x - mx.x); sm.y += expf(lg.y - mx.y);
        sm.z += expf(lg.z - mx.z); sm.w += expf(lg.w - mx.w);
    }
    #pragma unroll
    for (int off = 16; off; off >>= 1) {
        sm.x += __shfl_xor_sync(0xffffffffu, sm.x, off);
        sm.y += __shfl_xor_sync(0xffffffffu, sm.y, off);
        sm.z += __shfl_xor_sync(0xffffffffu, sm.z, off);
        sm.w += __shfl_xor_sync(0xffffffffu, sm.w, off);
    }
    const int head = lane >> 3;
    const float mh = sel4(mx, head);
    const float ih = 1.f / (sel4(sm, head) + 1e-16f);
    float acc[8];
    #pragma unroll
    for (int j = 0; j < 8; j++) acc[j] = 0.f;
    for (int idx = p0; idx < p1; idx++) {
        int e = g_csr_e[idx];
        int s = g_csr_s[idx];
        float4 lg = *(const float4*)(g_logits + (size_t)e*HEADS);
        float w = expf(sel4(lg, head) - mh) * ih;
        const float* px = g_xlr + (size_t)s*512 + lane*8;
        float4 x0 = *(const float4*)(px);
        float4 x1 = *(const float4*)(px+4);
        acc[0] += w*x0.x; acc[1] += w*x0.y; acc[2] += w*x0.z; acc[3] += w*x0.w;
        acc[4] += w*x1.x; acc[5] += w*x1.y; acc[6] += w*x1.z; acc[7] += w*x1.w;
    }
    float* ph = g_h + (size_t)n*HID + lane*8;
    float4 h0 = *(const float4*)(ph);
    float4 h1 = *(const float4*)(ph+4);
    float4 b0 = *(const float4*)(bconv + lane*8);
    float4 b1 = *(const float4*)(bconv + lane*8 + 4);
    float hv[8] = {h0.x,h0.y,h0.z,h0.w,h1.x,h1.y,h1.z,h1.w};
    float bv[8] = {b0.x,b0.y,b0.z,b0.w,b1.x,b1.y,b1.z,b1.w};
    float s_ = 0.f, q_ = 0.f;
    float out8[8];
    #pragma unroll
    for (int j = 0; j < 8; j++) {
        float v  = acc[j] + bv[j];
        float el = v > 0.f ? v : (expf(v) - 1.f);
        float t  = hv[j] + el;
        out8[j] = t; s_ += t; q_ += t*t;
    }
    *(float4*)(ph)   = make_float4(out8[0],out8[1],out8[2],out8[3]);
    *(float4*)(ph+4) = make_float4(out8[4],out8[5],out8[6],out8[7]);
    #pragma unroll
    for (int off = 16; off; off >>= 1) {
        s_ += __shfl_down_sync(0xffffffffu, s_, off);
        q_ += __shfl_down_sync(0xffffffffu, q_, off);
    }
    __shared__ float ss[8], sq[8];
    int w = threadIdx.x >> 5;
    if (lane == 0) { ss[w] = s_; sq[w] = q_; }
    __syncthreads();
    if (threadIdx.x == 0) {
        float S = 0.f, Q = 0.f;
        #pragma unroll
        for (int i = 0; i < 8; i++) { S += ss[i]; Q += sq[i]; }
        atomicAdd(&g_red[0], (double)S);
        atomicAdd(&g_red[1], (double)Q);
    }
}

__global__ void k_norm(const float* __restrict__ lnw, const float* __restrict__ lnb){
    int idx = blockIdx.x*blockDim.x + threadIdx.x;
    if (idx >= TOT_H) return;
    int c = idx & (HID-1);
    double M  = (double)TOT_H;
    double mu = g_red[0] / M;
    double var = g_red[1] / M - mu*mu;
    if (var < 0.0) var = 0.0;
    float rs = (float)(1.0 / (sqrt(var) + 1e-5));
    g_h[idx] = (g_h[idx] - (float)mu) * rs * lnw[c] + lnb[c];
}

// ---------------- launcher ---------------------------------------------------
extern "C" void kernel_launch(void* const* d_in, const int* in_sizes, int n_in,
                              void* d_out, int out_size)
{
    const float* x     = (const float*)d_in[0];
    const int*   ei    = (const int*)  d_in[1];
    const float* ea    = (const float*)d_in[2];
    const float* w_in  = (const float*)d_in[3];
    const float* b_in  = (const float*)d_in[4];
    const float* wl    = (const float*)d_in[5];
    const float* wr    = (const float*)d_in[6];
    const float* we    = (const float*)d_in[7];
    const float* att   = (const float*)d_in[8];
    const float* bconv = (const float*)d_in[9];
    const float* lnw   = (const float*)d_in[10];
    const float* lnb   = (const float*)d_in[11];
    const float* wout  = (const float*)d_in[12];
    const float* bout  = (const float*)d_in[13];
    float* out = (float*)d_out;
    const int* srcA = ei;
    const int* dstA = ei + NE;

    float *p_h, *p_xlr, *p_loop, *p_deg, *p_winT, *p_wcatT, *p_woutT;
    cudaGetSymbolAddress((void**)&p_h,     g_h);
    cudaGetSymbolAddress((void**)&p_xlr,   g_xlr);
    cudaGetSymbolAddress((void**)&p_loop,  g_loopea);
    cudaGetSymbolAddress((void**)&p_deg,   g_deg);
    cudaGetSymbolAddress((void**)&p_winT,  g_winT);
    cudaGetSymbolAddress((void**)&p_wcatT, g_wcatT);
    cudaGetSymbolAddress((void**)&p_woutT, g_woutT);

    // self-loop edge attrs + CSR build
    k_zero_f<<<(unsigned)(((size_t)N_NODES*EDIM + 511)/512), 512>>>(p_loop, (size_t)N_NODES*EDIM);
    k_zero_f<<<(N_NODES + 511)/512, 512>>>(p_deg, (size_t)N_NODES);
    k_degree<<<(NE*8 + 255)/256, 256>>>(dstA, ea);
    k_divloop<<<(N_NODES*EDIM + 255)/256, 256>>>();
    k_scan<<<1, 1024>>>();
    k_scatter<<<(ETOT + 255)/256, 256>>>(srcA, dstA);

    // weight prep (transpose + tf32 round)
    k_transpose<<<dim3(HID/32, DIN/32), 256>>>(w_in, p_winT, DIN, HID);
    k_transpose<<<dim3(HID/32, HID/32), 256>>>(wout, p_woutT, HID, HID);

    dim3 gIn (HID/128, (N_NODES + 127)/128);
    dim3 gXlr(512/128, (N_NODES + 127)/128);
    tgemm<<<gIn, 256>>>(x, p_winT, b_in, p_h, N_NODES, DIN, HID, 1);

    for (int l = 0; l < NLAYER; l++) {
        k_transpose<<<dim3(HID/32, HID/32), 256>>>(wl + (size_t)l*HID*HID, p_wcatT, HID, HID);
        k_transpose<<<dim3(HID/32, HID/32), 256>>>(wr + (size_t)l*HID*HID,
                                                   p_wcatT + (size_t)HID*HID, HID, HID);
        k_weT<<<(HID*EDIM + 255)/256, 256>>>(we + (size_t)l*EDIM*HID);

        tgemm<<<gXlr, 256>>>(p_h, p_wcatT, nullptr, p_xlr, N_NODES, HID, 512, 0);
        k_eplogits<<<(ETOT + 127)/128, 256>>>(srcA, dstA, ea,
                                              att + (size_t)l*HEADS*CDIM);
        k_zero_red<<<1, 32>>>();
        k_nodeagg<<<N_NODES/8, 256>>>(bconv + (size_t)l*HID);
        k_norm<<<TOT_H/256, 256>>>(lnw + (size_t)l*HID, lnb + (size_t)l*HID);
    }
    tgemm<<<gIn, 256>>>(p_h, p_woutT, bout, out, N_NODES, HID, HID, 0);
}